// round 9
// baseline (speedup 1.0000x reference)
#include <cuda_runtime.h>
#include <math.h>

#define BS   64
#define CIN  256
#define II   1024
#define J    10
#define D    32
#define NTILE 4
#define TILE_I 256   // II / NTILE

typedef unsigned long long ull;

// ---------------- scratch (static device globals; no allocation) ----------------
__device__ float g_xsum [BS*CIN];
__device__ float g_u    [BS*J*CIN];          // accumulated u_j = W_j^T v_j
__device__ float g_vb   [BS*J];
__device__ float g_ypart[BS*NTILE*J*CIN];
__device__ float g_cpart[BS*NTILE*J];

// ---------------- f32x2 helpers ----------------
static __device__ __forceinline__ void ffma2(ull &d, ull a, ull b) {
    asm("fma.rn.f32x2 %0, %1, %2, %0;" : "+l"(d) : "l"(a), "l"(b));
}
static __device__ __forceinline__ ull add2(ull a, ull b) {
    ull r;
    asm("add.rn.f32x2 %0, %1, %2;" : "=l"(r) : "l"(a), "l"(b));
    return r;
}
static __device__ __forceinline__ ull dup2(float x) {
    unsigned int u = __float_as_uint(x);
    return ((ull)u << 32) | (ull)u;
}
static __device__ __forceinline__ float lo2(ull v) {
    return __uint_as_float((unsigned int)(v & 0xffffffffu));
}
static __device__ __forceinline__ float hi2(ull v) {
    return __uint_as_float((unsigned int)(v >> 32));
}

// ---------------- K1: xsum[b,c] = sum_i x[b,c,i] ----------------
__global__ void k_xsum(const float* __restrict__ x) {
    int warp = (blockIdx.x * blockDim.x + threadIdx.x) >> 5;   // row = b*CIN + c
    int lane = threadIdx.x & 31;
    if (warp >= BS * CIN) return;
    const float4* row = (const float4*)(x + (size_t)warp * II);
    float s = 0.0f;
    #pragma unroll
    for (int k = 0; k < II / 128; k++) {
        float4 v = row[k * 32 + lane];
        s += v.x + v.y + v.z + v.w;
    }
    #pragma unroll
    for (int off = 16; off; off >>= 1) s += __shfl_xor_sync(0xffffffffu, s, off);
    if (lane == 0) g_xsum[warp] = s;
}

// ---------------- K_sv3: register-W, single W read, per (b,j) block ----------
// grid (J, BS), 256 threads (thread = channel c). mode: 0 iter1, 1 mid, 2 final
__global__ void __launch_bounds__(256) k_sv3(const float* __restrict__ W,
                                             const float* __restrict__ Wb,
                                             float* __restrict__ out, int mode) {
    int j = blockIdx.x, b = blockIdx.y, t = threadIdx.x;
    int w = t >> 5, l = t & 31;
    __shared__ float wp[D][9];     // warp partials, padded
    __shared__ float vsm[D];
    __shared__ float csum_s;

    // W_j column for this thread -> 32 regs (one coalesced LDG per d, MLP=32)
    float wr[D];
    const float* Wj = W + (size_t)j * D * CIN + t;
    #pragma unroll
    for (int d = 0; d < D; d++) wr[d] = Wj[(size_t)d * CIN];

    // y[c] for this (b,j)
    float y;
    if (mode == 0) {
        y = g_xsum[b * CIN + t] * (1.0f / (float)J);
        if (t == 0) csum_s = (float)II / (float)J;
    } else {
        const float* yp = g_ypart + (((size_t)b * NTILE) * J + j) * CIN + t;
        y = yp[0] + yp[(size_t)J * CIN] + yp[2 * (size_t)J * CIN] + yp[3 * (size_t)J * CIN];
        if (t == 0) {
            const float* cp = g_cpart + (b * NTILE) * J + j;
            csum_s = cp[0] + cp[J] + cp[2 * J] + cp[3 * J];
        }
    }

    // s[d] = sum_c W[d,c]*y[c]: per-warp shfl reduce over this warp's 32 c's
    #pragma unroll
    for (int d = 0; d < D; d++) {
        float p = wr[d] * y;
        #pragma unroll
        for (int o = 16; o; o >>= 1) p += __shfl_xor_sync(0xffffffffu, p, o);
        if (l == 0) wp[d][w] = p;
    }
    __syncthreads();

    // warp 0: finish s, squash, v, vb/out
    if (w == 0) {
        float s = 0.0f;
        #pragma unroll
        for (int q = 0; q < 8; q++) s += wp[l][q];
        s += csum_s * Wb[j * D + l];
        float ns = s * s;
        #pragma unroll
        for (int o = 16; o; o >>= 1) ns += __shfl_xor_sync(0xffffffffu, ns, o);
        float coef = ns / ((1.0f + ns) * sqrtf(ns));
        float v = s * coef;
        vsm[l] = v;
        if (mode == 2) {
            out[(b * J + j) * D + l] = v;
        } else {
            float pv = v * Wb[j * D + l];
            #pragma unroll
            for (int o = 16; o; o >>= 1) pv += __shfl_xor_sync(0xffffffffu, pv, o);
            if (l == 0) {
                int gi = b * J + j;
                g_vb[gi] = (mode == 0) ? pv : g_vb[gi] + pv;
            }
        }
    }
    __syncthreads();

    // u[c] = sum_d v[d]*W[d,c] from registers (broadcast LDS for v)
    if (mode != 2) {
        float u = 0.0f;
        #pragma unroll
        for (int d = 0; d < D; d++) u = fmaf(vsm[d], wr[d], u);
        size_t gi = ((size_t)b * J + j) * CIN + t;
        g_u[gi] = (mode == 0) ? u : g_u[gi] + u;
    }
}

// ---------------- K_pass: logits -> softmax -> partial y, csum ----------------
// grid (NTILE, BS), 256 threads.
// Phase A: thread = (warp w, lane l): cg = l>>3 covers c in [cg*64, cg*64+64),
//          qi = l&7 -> 4 i's at ib = w*32 + qi*4 (LDG.128 per c), shfl combine.
// Phase B: thread = channel c; x staged in 16-i chunks (stride-20 rows).
__global__ void __launch_bounds__(256) k_pass(const float* __restrict__ x) {
    __shared__ __align__(16) char  sm1[20480];          // uperm (A) / xsm (B)
    __shared__ __align__(16) float cssm[J * TILE_I];    // 10240B
    __shared__ float vbs[J];

    ull*   uperm = (ull*)sm1;    // [j*256 + (c&63)*4 + (c>>6)], dup-packed
    float* xsm   = (float*)sm1;  // [row*20 + i] staged chunk (aliased)

    int b = blockIdx.y, tile = blockIdx.x, t = threadIdx.x;
    int w = t >> 5, l = t & 31;

    const float* gu = g_u + (size_t)b * J * CIN;
    #pragma unroll
    for (int k = 0; k < J; k++)
        uperm[k * 256 + (t & 63) * 4 + (t >> 6)] = dup2(gu[k * 256 + t]);
    if (t < J) vbs[t] = g_vb[b * J + t];
    __syncthreads();

    const float* xb = x + (size_t)b * CIN * II;
    int i0 = tile * TILE_I;
    int cg = l >> 3, qi = l & 7;
    int ib = w * 32 + qi * 4;      // this thread's first local i

    // ---- phase A ----
    ull a0[J], a1[J];
    #pragma unroll
    for (int j = 0; j < J; j++) { a0[j] = 0ull; a1[j] = 0ull; }
    {
        const float* xp = xb + (size_t)cg * 64 * II + i0 + ib;
        #pragma unroll 4
        for (int cc = 0; cc < 64; cc++) {
            ulonglong2 xv = *(const ulonglong2*)(xp + (size_t)cc * II);
            const ull* up = uperm + cc * 4 + cg;
            #pragma unroll
            for (int j = 0; j < J; j++) {
                ull ud = up[j * 256];
                ffma2(a0[j], ud, xv.x);
                ffma2(a1[j], ud, xv.y);
            }
        }
    }
    // combine the 4 c-groups (lanes xor 8, xor 16)
    #pragma unroll
    for (int j = 0; j < J; j++) {
        a0[j] = add2(a0[j], __shfl_xor_sync(0xffffffffu, a0[j], 8));
        a1[j] = add2(a1[j], __shfl_xor_sync(0xffffffffu, a1[j], 8));
        a0[j] = add2(a0[j], __shfl_xor_sync(0xffffffffu, a0[j], 16));
        a1[j] = add2(a1[j], __shfl_xor_sync(0xffffffffu, a1[j], 16));
    }
    if (cg == 0) {
        float lg[J][4];
        #pragma unroll
        for (int j = 0; j < J; j++) {
            lg[j][0] = lo2(a0[j]) + vbs[j];
            lg[j][1] = hi2(a0[j]) + vbs[j];
            lg[j][2] = lo2(a1[j]) + vbs[j];
            lg[j][3] = hi2(a1[j]) + vbs[j];
        }
        float r[4];
        #pragma unroll
        for (int i = 0; i < 4; i++) {
            float m = lg[0][i];
            #pragma unroll
            for (int j = 1; j < J; j++) m = fmaxf(m, lg[j][i]);
            float s = 0.0f;
            #pragma unroll
            for (int j = 0; j < J; j++) { lg[j][i] = __expf(lg[j][i] - m); s += lg[j][i]; }
            r[i] = 1.0f / s;
        }
        #pragma unroll
        for (int j = 0; j < J; j++) {
            float4 cv = make_float4(lg[j][0] * r[0], lg[j][1] * r[1],
                                    lg[j][2] * r[2], lg[j][3] * r[3]);
            *(float4*)(cssm + j * TILE_I + ib) = cv;
        }
    }
    __syncthreads();

    // ---- csum partials ----
    for (int j = w; j < J; j += 8) {
        const float4* p4 = (const float4*)(cssm + j * TILE_I);
        float4 A = p4[l * 2], B4 = p4[l * 2 + 1];
        float sc = A.x + A.y + A.z + A.w + B4.x + B4.y + B4.z + B4.w;
        #pragma unroll
        for (int o = 16; o; o >>= 1) sc += __shfl_xor_sync(0xffffffffu, sc, o);
        if (l == 0) g_cpart[(b * NTILE + tile) * J + j] = sc;
    }

    // ---- phase B: y[j][c=t] = sum_i c[j,i]*x[c,i] over 16-i staged chunks ----
    ull y0[J], y1[J];
    #pragma unroll
    for (int j = 0; j < J; j++) { y0[j] = 0ull; y1[j] = 0ull; }

    int srow = t >> 2, sq = t & 3;
    #pragma unroll 1
    for (int ch = 0; ch < TILE_I / 16; ch++) {
        __syncthreads();   // prev chunk consumed (first iter: uperm reads done)
        #pragma unroll
        for (int s = 0; s < 4; s++) {
            int row = s * 64 + srow;
            float4 v = *(const float4*)(xb + (size_t)row * II + i0 + ch * 16 + sq * 4);
            *(float4*)(xsm + row * 20 + sq * 4) = v;
        }
        __syncthreads();
        #pragma unroll
        for (int g = 0; g < 4; g++) {
            ulonglong2 xv = *(const ulonglong2*)(xsm + t * 20 + g * 4);
            int ii = ch * 16 + g * 4;
            #pragma unroll
            for (int j = 0; j < J; j++) {
                ulonglong2 cv = *(const ulonglong2*)(cssm + j * TILE_I + ii);  // uniform
                ffma2(y0[j], cv.x, xv.x);
                ffma2(y1[j], cv.y, xv.y);
            }
        }
    }
    #pragma unroll
    for (int j = 0; j < J; j++)
        g_ypart[(((size_t)b * NTILE + tile) * J + j) * CIN + t] =
            (lo2(y0[j]) + hi2(y0[j])) + (lo2(y1[j]) + hi2(y1[j]));
}

// ---------------- launch ----------------
extern "C" void kernel_launch(void* const* d_in, const int* in_sizes, int n_in,
                              void* d_out, int out_size) {
    const float* x  = (const float*)d_in[0];   // [64,256,32,32]
    const float* W  = (const float*)d_in[1];   // [320,256]
    const float* Wb = (const float*)d_in[2];   // [320]
    float* out = (float*)d_out;                // [64,10,32]

    k_xsum<<<BS * CIN / 8, 256>>>(x);
    k_sv3 <<<dim3(J, BS), 256>>>(W, Wb, out, 0);   // iter1: v1, u1, vb1
    k_pass<<<dim3(NTILE, BS), 256>>>(x);           // iter2 logits+softmax+y
    k_sv3 <<<dim3(J, BS), 256>>>(W, Wb, out, 1);   // iter2: v2, u+=, vb+=
    k_pass<<<dim3(NTILE, BS), 256>>>(x);           // iter3 logits+softmax+y
    k_sv3 <<<dim3(J, BS), 256>>>(W, Wb, out, 2);   // iter3: v3 -> out
}